// round 11
// baseline (speedup 1.0000x reference)
#include <cuda_runtime.h>
#include <cuda_bf16.h>
#include <cstdint>

// Problem constants
#define NR   16384
#define DIN  1024
#define DH   4096
#define DZ   256
#define KCB  4096
#define RESCUE_CAP 8192

// ===================== scratch (device globals) ==============================
__device__ __nv_bfloat16 g_xs [2u * NR * DIN];
__device__ __nv_bfloat16 g_w1s[2u * DH * DIN];
__device__ __nv_bfloat16 g_w2s[2u * DH * DH];
__device__ __nv_bfloat16 g_w3s[2u * DZ * DH];
__device__ __nv_bfloat16 g_h1s[2ull * NR * DH];
__device__ __nv_bfloat16 g_h2s[2ull * NR * DH];
__device__ float g_z [NR * DZ];
__device__ float g_znorm[NR];
__device__ float g_cnorm[KCB];
__device__ float g_pval [4 * NR];
__device__ float g_pval2[4 * NR];
__device__ int   g_pidx[4 * NR];
__device__ float g_minval[NR];
__device__ int   g_minidx[NR];
__device__ int   g_flagcnt;
__device__ int   g_flaglist[RESCUE_CAP];

// ===================== helpers ===============================================
__device__ __forceinline__ uint32_t smem_to_u32(const void* smem_ptr) {
    uint32_t addr;
    asm("{ .reg .u64 tmp; cvta.to.shared.u64 tmp, %1; cvt.u32.u64 %0, tmp; }"
        : "=r"(addr) : "l"(smem_ptr));
    return addr;
}
__device__ __forceinline__ void split2(float v, __nv_bfloat16& h, __nv_bfloat16& m) {
    h = __float2bfloat16(v);
    m = __float2bfloat16(v - __bfloat162float(h));
}
__device__ __forceinline__ uint32_t pk2(__nv_bfloat16 a, __nv_bfloat16 b) {
    return (uint32_t)__bfloat16_as_ushort(a) | ((uint32_t)__bfloat16_as_ushort(b) << 16);
}

#define LDMX4(r, addr) \
    asm volatile("ldmatrix.sync.aligned.m8n8.x4.shared.b16 {%0,%1,%2,%3}, [%4];" \
        : "=r"((r)[0]), "=r"((r)[1]), "=r"((r)[2]), "=r"((r)[3]) : "r"(addr))

#define MMA16816(d, a, b0, b1) \
    asm volatile("mma.sync.aligned.m16n8k16.row.col.f32.bf16.bf16.f32 " \
        "{%0,%1,%2,%3}, {%4,%5,%6,%7}, {%8,%9}, {%0,%1,%2,%3};" \
        : "+f"((d)[0]), "+f"((d)[1]), "+f"((d)[2]), "+f"((d)[3]) \
        : "r"((a)[0]), "r"((a)[1]), "r"((a)[2]), "r"((a)[3]), "r"(b0), "r"(b1))

// ===================== split kernels (2 limbs) ===============================
__global__ void split_kernel(const float* __restrict__ in, __nv_bfloat16* __restrict__ out,
                             size_t n, size_t ps)
{
    size_t i = ((size_t)blockIdx.x * blockDim.x + threadIdx.x) * 4;
    if (i >= n) return;
    float4 v = *(const float4*)(in + i);
    __nv_bfloat16 h[4], m[4];
    split2(v.x, h[0], m[0]);
    split2(v.y, h[1], m[1]);
    split2(v.z, h[2], m[2]);
    split2(v.w, h[3], m[3]);
    *(uint2*)(out + i)      = make_uint2(pk2(h[0],h[1]), pk2(h[2],h[3]));
    *(uint2*)(out + ps + i) = make_uint2(pk2(m[0],m[1]), pk2(m[2],m[3]));
}

// split + transpose weight W[K][N] fp32 -> out[2][N][K] bf16 limbs
__global__ void splitT_kernel(const float* __restrict__ W, __nv_bfloat16* __restrict__ out,
                              int K, int N, size_t ps)
{
    __shared__ float tile[32][33];
    int k0 = blockIdx.y * 32, n0 = blockIdx.x * 32;
    int tx = threadIdx.x, ty = threadIdx.y;   // 32 x 8
#pragma unroll
    for (int dy = 0; dy < 32; dy += 8)
        tile[ty + dy][tx] = W[(size_t)(k0 + ty + dy) * N + n0 + tx];
    __syncthreads();
#pragma unroll
    for (int dy = 0; dy < 32; dy += 8) {
        int n = n0 + ty + dy, k = k0 + tx;
        float v = tile[tx][ty + dy];
        __nv_bfloat16 h, m;
        split2(v, h, m);
        size_t off = (size_t)n * K + k;
        out[off]      = h;
        out[ps + off] = m;
    }
}

// ===================== bf16x2 HMMA (mma.sync) GEMM, 3 products ===============
// D[M,N] fp32 = ahh*bhh + ahh*bm + am*bhh (mm dropped, err ~2^-17).
// CTA 128x128, BK=32, 2-stage cp.async, 8 warps (warp tile 64x32), 2 CTA/SM.
// SMEM plane tile: 128 rows x 32 bf16, row pitch 80B (conflict-free ldmatrix).
#define PLB  (128 * 80)           // 10240 B per plane tile
#define STG  (4 * PLB)            // 40960 B per stage (2 A planes + 2 B planes)
#define GEMM_SMEM_BYTES (2 * STG) // 81920

__global__ __launch_bounds__(256, 2)
void gemm_b2_mma_kernel(const __nv_bfloat16* __restrict__ Ap, size_t aps,
                        const __nv_bfloat16* __restrict__ Bp, size_t bps,
                        const float* __restrict__ bias,
                        __nv_bfloat16* __restrict__ outp, size_t ops,
                        float* __restrict__ outf,
                        int Kg, int Ng, int relu)
{
    extern __shared__ char smem[];
    const uint32_t sb = smem_to_u32(smem);
    const int tid = threadIdx.x;
    const int wid = tid >> 5, lane = tid & 31;
    const int wm = wid >> 2;          // 0..1  (warp row: 64 rows)
    const int wn = wid & 3;           // 0..3  (warp col: 32 cols)
    const int m0 = blockIdx.y * 128, n0 = blockIdx.x * 128;

    const int brow  = (lane & 7) + ((lane >> 3) & 1) * 8;  // 0..15
    const int chalf = lane >> 4;                           // 0..1

    const __nv_bfloat16* Abase = Ap + (size_t)m0 * Kg;
    const __nv_bfloat16* Bbase = Bp + (size_t)n0 * Kg;
    const int nIt = Kg >> 5;

    // stage loader: 4 planes x 128 rows x 4 chunks(16B) = 2048 chunks
    auto load_stage = [&](int it) {
        const uint32_t dstb = sb + (uint32_t)(it & 1) * STG;
        const int k0 = it << 5;
#pragma unroll
        for (int t = 0; t < 8; t++) {
            int id = tid + t * 256;
            int p = id >> 9;                 // plane 0..3
            int rem = id & 511;
            int r = rem >> 2;                // row 0..127
            int c = rem & 3;                 // chunk 0..3 (8 bf16 each)
            const __nv_bfloat16* src;
            if (p < 2) src = Abase + (size_t)p * aps + (size_t)r * Kg + k0 + c * 8;
            else       src = Bbase + (size_t)(p - 2) * bps + (size_t)r * Kg + k0 + c * 8;
            uint32_t dst = dstb + (uint32_t)p * PLB + (uint32_t)(r * 80 + c * 16);
            asm volatile("cp.async.cg.shared.global [%0], [%1], 16;"
                         :: "r"(dst), "l"(src) : "memory");
        }
        asm volatile("cp.async.commit_group;" ::: "memory");
    };

    float acc[4][4][4];
#pragma unroll
    for (int i = 0; i < 4; i++)
#pragma unroll
        for (int j = 0; j < 4; j++)
#pragma unroll
            for (int q = 0; q < 4; q++) acc[i][j][q] = 0.f;

    // limb product schedule: (A plane, B plane): hh, hm, mh
    const int PA[3] = {0, 0, 1};
    const int PB[3] = {0, 1, 0};

    load_stage(0);
    if (nIt > 1) load_stage(1);

    for (int it = 0; it < nIt; it++) {
        if (it + 1 < nIt) asm volatile("cp.async.wait_group 1;" ::: "memory");
        else              asm volatile("cp.async.wait_group 0;" ::: "memory");
        __syncthreads();

        const uint32_t sA = sb + (uint32_t)(it & 1) * STG;
        const uint32_t sB = sA + 2 * PLB;

#pragma unroll
        for (int kk2 = 0; kk2 < 2; kk2++) {      // two k16 halves of BK=32
            uint32_t Bf[2][2][4];
#pragma unroll
            for (int p = 0; p < 2; p++)
#pragma unroll
                for (int nt = 0; nt < 2; nt++) {
                    uint32_t addr = sB + (uint32_t)p * PLB
                                  + (uint32_t)((wn * 32 + nt * 16 + brow) * 80
                                  + (kk2 * 2 + chalf) * 16);
                    LDMX4(Bf[p][nt], addr);
                }
#pragma unroll
            for (int mi = 0; mi < 4; mi++) {
                uint32_t Af[2][4];
#pragma unroll
                for (int p = 0; p < 2; p++) {
                    uint32_t addr = sA + (uint32_t)p * PLB
                                  + (uint32_t)((wm * 64 + mi * 16 + brow) * 80
                                  + (kk2 * 2 + chalf) * 16);
                    LDMX4(Af[p], addr);
                }
#pragma unroll
                for (int c = 0; c < 3; c++) {
#pragma unroll
                    for (int ni = 0; ni < 4; ni++) {
                        uint32_t b0 = Bf[PB[c]][ni >> 1][ni & 1];
                        uint32_t b1 = Bf[PB[c]][ni >> 1][2 + (ni & 1)];
                        MMA16816(acc[mi][ni], Af[PA[c]], b0, b1);
                    }
                }
            }
        }
        __syncthreads();
        if (it + 2 < nIt) load_stage(it + 2);
    }

    // ---- epilogue ----
    const int rbase = m0 + wm * 64 + (lane >> 2);
    const int cbase = n0 + wn * 32 + (lane & 3) * 2;
#pragma unroll
    for (int mi = 0; mi < 4; mi++) {
#pragma unroll
        for (int ni = 0; ni < 4; ni++) {
            int row = rbase + mi * 16;
            int col = cbase + ni * 8;
            float b0 = bias[col], b1 = bias[col + 1];
            float v00 = acc[mi][ni][0] + b0, v01 = acc[mi][ni][1] + b1;
            float v10 = acc[mi][ni][2] + b0, v11 = acc[mi][ni][3] + b1;
            if (relu) {
                v00 = fmaxf(v00, 0.f); v01 = fmaxf(v01, 0.f);
                v10 = fmaxf(v10, 0.f); v11 = fmaxf(v11, 0.f);
            }
            size_t o0 = (size_t)row * Ng + col;
            size_t o1 = (size_t)(row + 8) * Ng + col;
            if (outf) {
                *(float2*)(outf + o0) = make_float2(v00, v01);
                *(float2*)(outf + o1) = make_float2(v10, v11);
            } else {
                __nv_bfloat16 h0, m_0, h1, m_1;
                split2(v00, h0, m_0); split2(v01, h1, m_1);
                *(uint32_t*)(outp + o0)       = pk2(h0, h1);
                *(uint32_t*)(outp + ops + o0) = pk2(m_0, m_1);
                split2(v10, h0, m_0); split2(v11, h1, m_1);
                *(uint32_t*)(outp + o1)       = pk2(h0, h1);
                *(uint32_t*)(outp + ops + o1) = pk2(m_0, m_1);
            }
        }
    }
}

// ===================== fp32 distance path w/ top-2 (verified) ================
__global__ void rownorm256_kernel(const float* __restrict__ X, float* __restrict__ out, int rows)
{
    int gw   = (blockIdx.x * blockDim.x + threadIdx.x) >> 5;
    int lane = threadIdx.x & 31;
    if (gw >= rows) return;
    const float* row = X + (size_t)gw * 256;
    float s = 0.f;
    for (int c = lane * 4; c < 256; c += 128) {
        float4 v = *(const float4*)&row[c];
        s += v.x * v.x + v.y * v.y + v.z * v.z + v.w * v.w;
    }
#pragma unroll
    for (int o = 16; o; o >>= 1) s += __shfl_xor_sync(0xffffffffu, s, o);
    if (!lane) out[gw] = s;
}

__global__ __launch_bounds__(256)
void distmin_kernel(const float* __restrict__ Z, const float* __restrict__ CB,
                    const float* __restrict__ cnorm,
                    float* __restrict__ pval, float* __restrict__ pval2,
                    int* __restrict__ pidx)
{
    const int BM = 128, BN = 128, BK = 16, KD = 256, JG = 1024;
    __shared__ float As[BK][BM];
    __shared__ float Bs[BK][BN];
    __shared__ float s_rv [BM][17];
    __shared__ float s_rv2[BM][17];
    __shared__ int   s_ri [BM][17];
    __shared__ float s_bestv[BM];
    __shared__ float s_bestv2[BM];
    __shared__ int   s_besti[BM];

    const int tid = threadIdx.x;
    const int tm = tid >> 4, tn = tid & 15;
    const int bm  = blockIdx.y;
    const int grp = blockIdx.x;

    if (tid < BM) { s_bestv[tid] = 3.4e38f; s_bestv2[tid] = 3.4e38f; s_besti[tid] = 0; }

    const float* Ablk = Z + (size_t)bm * BM * KD;
    const int t_row = tid >> 2;
    const int t_col = (tid & 3) * 4;

    for (int j0 = grp * JG; j0 < grp * JG + JG; j0 += BN) {
        const float* Bblk = CB + (size_t)j0 * KD;
        float acc[8][8];
#pragma unroll
        for (int i = 0; i < 8; i++)
#pragma unroll
            for (int j = 0; j < 8; j++) acc[i][j] = 0.f;

        float4 pa0, pa1, pb0, pb1;
        pa0 = *(const float4*)(Ablk + (size_t)t_row        * KD + t_col);
        pa1 = *(const float4*)(Ablk + (size_t)(t_row + 64) * KD + t_col);
        pb0 = *(const float4*)(Bblk + (size_t)t_row        * KD + t_col);
        pb1 = *(const float4*)(Bblk + (size_t)(t_row + 64) * KD + t_col);

        for (int k0 = 0; k0 < KD; k0 += BK) {
            __syncthreads();
            As[t_col + 0][t_row]      = pa0.x;
            As[t_col + 1][t_row]      = pa0.y;
            As[t_col + 2][t_row]      = pa0.z;
            As[t_col + 3][t_row]      = pa0.w;
            As[t_col + 0][t_row + 64] = pa1.x;
            As[t_col + 1][t_row + 64] = pa1.y;
            As[t_col + 2][t_row + 64] = pa1.z;
            As[t_col + 3][t_row + 64] = pa1.w;
            Bs[t_col + 0][t_row]      = pb0.x;
            Bs[t_col + 1][t_row]      = pb0.y;
            Bs[t_col + 2][t_row]      = pb0.z;
            Bs[t_col + 3][t_row]      = pb0.w;
            Bs[t_col + 0][t_row + 64] = pb1.x;
            Bs[t_col + 1][t_row + 64] = pb1.y;
            Bs[t_col + 2][t_row + 64] = pb1.z;
            Bs[t_col + 3][t_row + 64] = pb1.w;
            __syncthreads();

            if (k0 + BK < KD) {
                const int kn = k0 + BK;
                pa0 = *(const float4*)(Ablk + (size_t)t_row        * KD + kn + t_col);
                pa1 = *(const float4*)(Ablk + (size_t)(t_row + 64) * KD + kn + t_col);
                pb0 = *(const float4*)(Bblk + (size_t)t_row        * KD + kn + t_col);
                pb1 = *(const float4*)(Bblk + (size_t)(t_row + 64) * KD + kn + t_col);
            }

#pragma unroll
            for (int kk = 0; kk < BK; kk++) {
                float a[8], b[8];
                *(float4*)&a[0] = *(const float4*)&As[kk][tm * 8];
                *(float4*)&a[4] = *(const float4*)&As[kk][tm * 8 + 4];
                *(float4*)&b[0] = *(const float4*)&Bs[kk][tn * 8];
                *(float4*)&b[4] = *(const float4*)&Bs[kk][tn * 8 + 4];
#pragma unroll
                for (int i = 0; i < 8; i++)
#pragma unroll
                    for (int j = 0; j < 8; j++) acc[i][j] += a[i] * b[j];
            }
        }
        __syncthreads();

        float cn[8];
        *(float4*)&cn[0] = *(const float4*)&cnorm[j0 + tn * 8];
        *(float4*)&cn[4] = *(const float4*)&cnorm[j0 + tn * 8 + 4];
#pragma unroll
        for (int i = 0; i < 8; i++) {
            float v1 = 3.4e38f, v2 = 3.4e38f; int i1 = 0;
#pragma unroll
            for (int j = 0; j < 8; j++) {
                float s = cn[j] - 2.f * acc[i][j];
                if (s < v1) { v2 = v1; v1 = s; i1 = j0 + tn * 8 + j; }
                else if (s < v2) v2 = s;
            }
            s_rv [tm * 8 + i][tn] = v1;
            s_rv2[tm * 8 + i][tn] = v2;
            s_ri [tm * 8 + i][tn] = i1;
        }
        __syncthreads();
        if (tid < BM) {
            float V1 = s_bestv[tid], V2 = s_bestv2[tid]; int I1 = s_besti[tid];
#pragma unroll
            for (int t = 0; t < 16; t++) {
                float v1c = s_rv[tid][t], v2c = s_rv2[tid][t];
                if (v1c < V1) { V2 = fminf(V1, v2c); V1 = v1c; I1 = s_ri[tid][t]; }
                else          { V2 = fminf(V2, v1c); }
            }
            s_bestv[tid] = V1; s_bestv2[tid] = V2; s_besti[tid] = I1;
        }
    }
    __syncthreads();
    if (tid < BM) {
        pval [(size_t)grp * NR + bm * BM + tid] = s_bestv[tid];
        pval2[(size_t)grp * NR + bm * BM + tid] = s_bestv2[tid];
        pidx [(size_t)grp * NR + bm * BM + tid] = s_besti[tid];
    }
}

__global__ void zero_flags_kernel() {
    if (threadIdx.x == 0 && blockIdx.x == 0) g_flagcnt = 0;
}

__global__ void combine_kernel(const float* __restrict__ pval, const float* __restrict__ pval2,
                               const int* __restrict__ pidx,
                               const float* __restrict__ znorm,
                               float* __restrict__ minval, int* __restrict__ minidx)
{
    int r = blockIdx.x * blockDim.x + threadIdx.x;
    if (r >= NR) return;
    float V1 = 3.4e38f, V2 = 3.4e38f; int I1 = 0;
#pragma unroll
    for (int g = 0; g < 4; g++) {
        float v1c = pval [(size_t)g * NR + r];
        float v2c = pval2[(size_t)g * NR + r];
        int   i1c = pidx [(size_t)g * NR + r];
        if (v1c < V1) { V2 = fminf(V1, v2c); V1 = v1c; I1 = i1c; }
        else          { V2 = fminf(V2, v1c); }
    }
    float zn = znorm[r];
    minval[r] = zn + V1;
    minidx[r] = I1;
    float d1 = zn + V1, d2 = zn + V2;
    // bf16x2 noise ~0.065 abs (128x the R4-calibrated bf16x3 noise); 17x margin
    if (d2 - d1 < 0.5f + 1e-3f * (fabsf(d1) + fabsf(d2))) {
        int s = atomicAdd(&g_flagcnt, 1);
        if (s < RESCUE_CAP) g_flaglist[s] = r;
    }
}

// ===================== fp32 exact rescue (verified) ==========================
__global__ __launch_bounds__(256)
void rescue_kernel(const float* __restrict__ x,
                   const float* __restrict__ W1, const float* __restrict__ b1,
                   const float* __restrict__ W2, const float* __restrict__ b2,
                   const float* __restrict__ W3, const float* __restrict__ b3,
                   const float* __restrict__ CB, const float* __restrict__ cnorm,
                   float* __restrict__ minval, int* __restrict__ minidx)
{
    __shared__ float sx[DIN];
    __shared__ float sh1[DH];
    __shared__ float sh2[DH];
    __shared__ float sz[DZ];
    __shared__ float rv[256];
    __shared__ int   ri[256];

    const int tid = threadIdx.x;
    int cnt = g_flagcnt;
    if (cnt > RESCUE_CAP) cnt = RESCUE_CAP;

    for (int q = blockIdx.x; q < cnt; q += gridDim.x) {
        int r = g_flaglist[q];
        for (int i = tid; i < DIN; i += 256) sx[i] = x[(size_t)r * DIN + i];
        __syncthreads();
        {
            float acc[16];
#pragma unroll
            for (int i = 0; i < 16; i++) acc[i] = b1[tid + 256 * i];
            for (int k = 0; k < DIN; k++) {
                float xv = sx[k];
                const float* wr = W1 + (size_t)k * DH;
#pragma unroll
                for (int i = 0; i < 16; i++) acc[i] += xv * wr[tid + 256 * i];
            }
#pragma unroll
            for (int i = 0; i < 16; i++) sh1[tid + 256 * i] = fmaxf(acc[i], 0.f);
        }
        __syncthreads();
        {
            float acc[16];
#pragma unroll
            for (int i = 0; i < 16; i++) acc[i] = b2[tid + 256 * i];
            for (int k = 0; k < DH; k++) {
                float hv = sh1[k];
                const float* wr = W2 + (size_t)k * DH;
#pragma unroll
                for (int i = 0; i < 16; i++) acc[i] += hv * wr[tid + 256 * i];
            }
#pragma unroll
            for (int i = 0; i < 16; i++) sh2[tid + 256 * i] = acc[i];
        }
        __syncthreads();
        {
            float acc = b3[tid];
            for (int k = 0; k < DH; k++) acc += sh2[k] * W3[(size_t)k * DZ + tid];
            sz[tid] = acc;
        }
        __syncthreads();
        rv[tid] = sz[tid] * sz[tid];
        __syncthreads();
        for (int w = 128; w > 0; w >>= 1) {
            if (tid < w) rv[tid] += rv[tid + w];
            __syncthreads();
        }
        float znorm_r = rv[0];
        __syncthreads();
        {
            float V = 3.4e38f; int I = 0;
            for (int jj = 0; jj < 16; jj++) {
                int j = tid * 16 + jj;
                const float* crow = CB + (size_t)j * DZ;
                float dot = 0.f;
                for (int k = 0; k < DZ; k += 4) {
                    float4 c4 = *(const float4*)(crow + k);
                    dot += sz[k] * c4.x + sz[k+1] * c4.y + sz[k+2] * c4.z + sz[k+3] * c4.w;
                }
                float s = cnorm[j] - 2.f * dot;
                if (s < V) { V = s; I = j; }
            }
            rv[tid] = V; ri[tid] = I;
        }
        __syncthreads();
        for (int w = 128; w > 0; w >>= 1) {
            if (tid < w) {
                if (rv[tid + w] < rv[tid] ||
                    (rv[tid + w] == rv[tid] && ri[tid + w] < ri[tid])) {
                    rv[tid] = rv[tid + w]; ri[tid] = ri[tid + w];
                }
            }
            __syncthreads();
        }
        if (tid == 0) {
            minval[r] = znorm_r + rv[0];
            minidx[r] = ri[0];
        }
        __syncthreads();
    }
}

// ===================== output kernels ========================================
__global__ void gather_kernel(const float* __restrict__ CB, const int* __restrict__ minidx,
                              float* __restrict__ out)
{
    int r = blockIdx.x;
    int c = threadIdx.x;
    float4 v = *(const float4*)&CB[(size_t)minidx[r] * DZ + c * 4];
    *(float4*)&out[(size_t)r * DZ + c * 4] = v;
}

__global__ void loss_kernel(const float* __restrict__ minval, float* __restrict__ out,
                            int out_size)
{
    __shared__ float sm[512];
    int t = threadIdx.x;
    float s = 0.f;
    for (int i = t; i < NR; i += 512) s += minval[i];
    sm[t] = s;
    __syncthreads();
    for (int w = 256; w > 0; w >>= 1) {
        if (t < w) sm[t] += sm[t + w];
        __syncthreads();
    }
    if (t == 0 && out_size > NR * DZ) out[NR * DZ] = 2.f * sm[0];
}

// ===================== launch ================================================
extern "C" void kernel_launch(void* const* d_in, const int* in_sizes, int n_in,
                              void* d_out, int out_size)
{
    const float* x  = (const float*)d_in[0];
    const float* W1 = (const float*)d_in[1];
    const float* b1 = (const float*)d_in[2];
    const float* W2 = (const float*)d_in[3];
    const float* b2 = (const float*)d_in[4];
    const float* W3 = (const float*)d_in[5];
    const float* b3 = (const float*)d_in[6];
    const float* CB = (const float*)d_in[7];
    float* out = (float*)d_out;

    __nv_bfloat16 *xs, *w1s, *w2s, *w3s, *h1s, *h2s;
    float *z, *znorm, *cnorm, *pval, *pval2, *minval;
    int *pidx, *minidx;
    cudaGetSymbolAddress((void**)&xs,  g_xs);
    cudaGetSymbolAddress((void**)&w1s, g_w1s);
    cudaGetSymbolAddress((void**)&w2s, g_w2s);
    cudaGetSymbolAddress((void**)&w3s, g_w3s);
    cudaGetSymbolAddress((void**)&h1s, g_h1s);
    cudaGetSymbolAddress((void**)&h2s, g_h2s);
    cudaGetSymbolAddress((void**)&z,      g_z);
    cudaGetSymbolAddress((void**)&znorm,  g_znorm);
    cudaGetSymbolAddress((void**)&cnorm,  g_cnorm);
    cudaGetSymbolAddress((void**)&pval,   g_pval);
    cudaGetSymbolAddress((void**)&pval2,  g_pval2);
    cudaGetSymbolAddress((void**)&pidx,   g_pidx);
    cudaGetSymbolAddress((void**)&minval, g_minval);
    cudaGetSymbolAddress((void**)&minidx, g_minidx);

    cudaFuncSetAttribute(gemm_b2_mma_kernel, cudaFuncAttributeMaxDynamicSharedMemorySize,
                         GEMM_SMEM_BYTES);

    const size_t ps_x  = (size_t)NR * DIN;
    const size_t ps_w1 = (size_t)DH * DIN;
    const size_t ps_w2 = (size_t)DH * DH;
    const size_t ps_w3 = (size_t)DZ * DH;
    const size_t ps_h  = (size_t)NR * DH;

    // 2-limb splits
    split_kernel<<<(unsigned)(ps_x / 4 / 256), 256>>>(x, xs, ps_x, ps_x);
    splitT_kernel<<<dim3(DH / 32, DIN / 32), dim3(32, 8)>>>(W1, w1s, DIN, DH, ps_w1);
    splitT_kernel<<<dim3(DH / 32, DH  / 32), dim3(32, 8)>>>(W2, w2s, DH,  DH, ps_w2);
    splitT_kernel<<<dim3(DZ / 32, DH  / 32), dim3(32, 8)>>>(W3, w3s, DH,  DZ, ps_w3);

    // MLP on HMMA (bf16x2, 3 products)
    gemm_b2_mma_kernel<<<dim3(DH / 128, NR / 128), 256, GEMM_SMEM_BYTES>>>(
        xs, ps_x, w1s, ps_w1, b1, h1s, ps_h, nullptr, DIN, DH, 1);
    gemm_b2_mma_kernel<<<dim3(DH / 128, NR / 128), 256, GEMM_SMEM_BYTES>>>(
        h1s, ps_h, w2s, ps_w2, b2, h2s, ps_h, nullptr, DH, DH, 0);
    gemm_b2_mma_kernel<<<dim3(DZ / 128, NR / 128), 256, GEMM_SMEM_BYTES>>>(
        h2s, ps_h, w3s, ps_w3, b3, nullptr, 0, z, DH, DZ, 0);

    // norms + fused distance/argmin (top-2)
    rownorm256_kernel<<<(KCB * 32) / 256, 256>>>(CB, cnorm, KCB);
    rownorm256_kernel<<<(NR  * 32) / 256, 256>>>(z,  znorm, NR);
    zero_flags_kernel<<<1, 32>>>();
    distmin_kernel<<<dim3(4, NR / 128), 256>>>(z, CB, cnorm, pval, pval2, pidx);
    combine_kernel<<<NR / 256, 256>>>(pval, pval2, pidx, znorm, minval, minidx);

    // exact fp32 rescue for near-tie rows
    rescue_kernel<<<512, 256>>>(x, W1, b1, W2, b2, W3, b3, CB, cnorm, minval, minidx);

    // outputs
    gather_kernel<<<NR, 64>>>(CB, minidx, out);
    loss_kernel<<<1, 512>>>(minval, out, out_size);
}

// round 12
// speedup vs baseline: 3.0500x; 3.0500x over previous
#include <cuda_runtime.h>
#include <cuda_bf16.h>
#include <cstdint>

// Problem constants
#define NR   16384
#define DIN  1024
#define DH   4096
#define DZ   256
#define KCB  4096
#define RESCUE_CAP 8192

// ===================== scratch (device globals) ==============================
__device__ __nv_bfloat16 g_xs [2u * NR * DIN];
__device__ __nv_bfloat16 g_w1s[2u * DH * DIN];
__device__ __nv_bfloat16 g_w2s[2u * DH * DH];
__device__ __nv_bfloat16 g_w3s[2u * DZ * DH];
__device__ __nv_bfloat16 g_h1s[2ull * NR * DH];
__device__ __nv_bfloat16 g_h2s[2ull * NR * DH];
__device__ float g_z [NR * DZ];
__device__ float g_znorm[NR];
__device__ float g_cnorm[KCB];
__device__ float g_pval [4 * NR];
__device__ float g_pval2[4 * NR];
__device__ int   g_pidx[4 * NR];
__device__ float g_minval[NR];
__device__ int   g_minidx[NR];
__device__ int   g_flagcnt;
__device__ int   g_flaglist[RESCUE_CAP];
// batched rescue buffers
__device__ float g_gx [(size_t)RESCUE_CAP * DIN];   // 32 MB
__device__ float g_gh1[(size_t)RESCUE_CAP * DH];    // 128 MB
__device__ float g_gh2[(size_t)RESCUE_CAP * DH];    // 128 MB
__device__ float g_gz [(size_t)RESCUE_CAP * DZ];    // 8 MB

// ===================== helpers ===============================================
__device__ __forceinline__ uint32_t smem_to_u32(const void* smem_ptr) {
    uint32_t addr;
    asm("{ .reg .u64 tmp; cvta.to.shared.u64 tmp, %1; cvt.u32.u64 %0, tmp; }"
        : "=r"(addr) : "l"(smem_ptr));
    return addr;
}
__device__ __forceinline__ void split2(float v, __nv_bfloat16& h, __nv_bfloat16& m) {
    h = __float2bfloat16(v);
    m = __float2bfloat16(v - __bfloat162float(h));
}
__device__ __forceinline__ uint32_t pk2(__nv_bfloat16 a, __nv_bfloat16 b) {
    return (uint32_t)__bfloat16_as_ushort(a) | ((uint32_t)__bfloat16_as_ushort(b) << 16);
}

#define LDMX4(r, addr) \
    asm volatile("ldmatrix.sync.aligned.m8n8.x4.shared.b16 {%0,%1,%2,%3}, [%4];" \
        : "=r"((r)[0]), "=r"((r)[1]), "=r"((r)[2]), "=r"((r)[3]) : "r"(addr))

#define MMA16816(d, a, b0, b1) \
    asm volatile("mma.sync.aligned.m16n8k16.row.col.f32.bf16.bf16.f32 " \
        "{%0,%1,%2,%3}, {%4,%5,%6,%7}, {%8,%9}, {%0,%1,%2,%3};" \
        : "+f"((d)[0]), "+f"((d)[1]), "+f"((d)[2]), "+f"((d)[3]) \
        : "r"((a)[0]), "r"((a)[1]), "r"((a)[2]), "r"((a)[3]), "r"(b0), "r"(b1))

// ===================== split kernels (2 limbs) ===============================
__global__ void split_kernel(const float* __restrict__ in, __nv_bfloat16* __restrict__ out,
                             size_t n, size_t ps)
{
    size_t i = ((size_t)blockIdx.x * blockDim.x + threadIdx.x) * 4;
    if (i >= n) return;
    float4 v = *(const float4*)(in + i);
    __nv_bfloat16 h[4], m[4];
    split2(v.x, h[0], m[0]);
    split2(v.y, h[1], m[1]);
    split2(v.z, h[2], m[2]);
    split2(v.w, h[3], m[3]);
    *(uint2*)(out + i)      = make_uint2(pk2(h[0],h[1]), pk2(h[2],h[3]));
    *(uint2*)(out + ps + i) = make_uint2(pk2(m[0],m[1]), pk2(m[2],m[3]));
}

__global__ void splitT_kernel(const float* __restrict__ W, __nv_bfloat16* __restrict__ out,
                              int K, int N, size_t ps)
{
    __shared__ float tile[32][33];
    int k0 = blockIdx.y * 32, n0 = blockIdx.x * 32;
    int tx = threadIdx.x, ty = threadIdx.y;   // 32 x 8
#pragma unroll
    for (int dy = 0; dy < 32; dy += 8)
        tile[ty + dy][tx] = W[(size_t)(k0 + ty + dy) * N + n0 + tx];
    __syncthreads();
#pragma unroll
    for (int dy = 0; dy < 32; dy += 8) {
        int n = n0 + ty + dy, k = k0 + tx;
        float v = tile[tx][ty + dy];
        __nv_bfloat16 h, m;
        split2(v, h, m);
        size_t off = (size_t)n * K + k;
        out[off]      = h;
        out[ps + off] = m;
    }
}

// ===================== bf16x2 HMMA GEMM, 3 products (R11-verified) ===========
#define PLB  (128 * 80)
#define STG  (4 * PLB)
#define GEMM_SMEM_BYTES (2 * STG) // 81920

__global__ __launch_bounds__(256, 2)
void gemm_b2_mma_kernel(const __nv_bfloat16* __restrict__ Ap, size_t aps,
                        const __nv_bfloat16* __restrict__ Bp, size_t bps,
                        const float* __restrict__ bias,
                        __nv_bfloat16* __restrict__ outp, size_t ops,
                        float* __restrict__ outf,
                        int Kg, int Ng, int relu)
{
    extern __shared__ char smem[];
    const uint32_t sb = smem_to_u32(smem);
    const int tid = threadIdx.x;
    const int wid = tid >> 5, lane = tid & 31;
    const int wm = wid >> 2;
    const int wn = wid & 3;
    const int m0 = blockIdx.y * 128, n0 = blockIdx.x * 128;

    const int brow  = (lane & 7) + ((lane >> 3) & 1) * 8;
    const int chalf = lane >> 4;

    const __nv_bfloat16* Abase = Ap + (size_t)m0 * Kg;
    const __nv_bfloat16* Bbase = Bp + (size_t)n0 * Kg;
    const int nIt = Kg >> 5;

    auto load_stage = [&](int it) {
        const uint32_t dstb = sb + (uint32_t)(it & 1) * STG;
        const int k0 = it << 5;
#pragma unroll
        for (int t = 0; t < 8; t++) {
            int id = tid + t * 256;
            int p = id >> 9;
            int rem = id & 511;
            int r = rem >> 2;
            int c = rem & 3;
            const __nv_bfloat16* src;
            if (p < 2) src = Abase + (size_t)p * aps + (size_t)r * Kg + k0 + c * 8;
            else       src = Bbase + (size_t)(p - 2) * bps + (size_t)r * Kg + k0 + c * 8;
            uint32_t dst = dstb + (uint32_t)p * PLB + (uint32_t)(r * 80 + c * 16);
            asm volatile("cp.async.cg.shared.global [%0], [%1], 16;"
                         :: "r"(dst), "l"(src) : "memory");
        }
        asm volatile("cp.async.commit_group;" ::: "memory");
    };

    float acc[4][4][4];
#pragma unroll
    for (int i = 0; i < 4; i++)
#pragma unroll
        for (int j = 0; j < 4; j++)
#pragma unroll
            for (int q = 0; q < 4; q++) acc[i][j][q] = 0.f;

    const int PA[3] = {0, 0, 1};
    const int PB[3] = {0, 1, 0};

    load_stage(0);
    if (nIt > 1) load_stage(1);

    for (int it = 0; it < nIt; it++) {
        if (it + 1 < nIt) asm volatile("cp.async.wait_group 1;" ::: "memory");
        else              asm volatile("cp.async.wait_group 0;" ::: "memory");
        __syncthreads();

        const uint32_t sA = sb + (uint32_t)(it & 1) * STG;
        const uint32_t sB = sA + 2 * PLB;

#pragma unroll
        for (int kk2 = 0; kk2 < 2; kk2++) {
            uint32_t Bf[2][2][4];
#pragma unroll
            for (int p = 0; p < 2; p++)
#pragma unroll
                for (int nt = 0; nt < 2; nt++) {
                    uint32_t addr = sB + (uint32_t)p * PLB
                                  + (uint32_t)((wn * 32 + nt * 16 + brow) * 80
                                  + (kk2 * 2 + chalf) * 16);
                    LDMX4(Bf[p][nt], addr);
                }
#pragma unroll
            for (int mi = 0; mi < 4; mi++) {
                uint32_t Af[2][4];
#pragma unroll
                for (int p = 0; p < 2; p++) {
                    uint32_t addr = sA + (uint32_t)p * PLB
                                  + (uint32_t)((wm * 64 + mi * 16 + brow) * 80
                                  + (kk2 * 2 + chalf) * 16);
                    LDMX4(Af[p], addr);
                }
#pragma unroll
                for (int c = 0; c < 3; c++) {
#pragma unroll
                    for (int ni = 0; ni < 4; ni++) {
                        uint32_t b0 = Bf[PB[c]][ni >> 1][ni & 1];
                        uint32_t b1 = Bf[PB[c]][ni >> 1][2 + (ni & 1)];
                        MMA16816(acc[mi][ni], Af[PA[c]], b0, b1);
                    }
                }
            }
        }
        __syncthreads();
        if (it + 2 < nIt) load_stage(it + 2);
    }

    const int rbase = m0 + wm * 64 + (lane >> 2);
    const int cbase = n0 + wn * 32 + (lane & 3) * 2;
#pragma unroll
    for (int mi = 0; mi < 4; mi++) {
#pragma unroll
        for (int ni = 0; ni < 4; ni++) {
            int row = rbase + mi * 16;
            int col = cbase + ni * 8;
            float b0 = bias[col], b1 = bias[col + 1];
            float v00 = acc[mi][ni][0] + b0, v01 = acc[mi][ni][1] + b1;
            float v10 = acc[mi][ni][2] + b0, v11 = acc[mi][ni][3] + b1;
            if (relu) {
                v00 = fmaxf(v00, 0.f); v01 = fmaxf(v01, 0.f);
                v10 = fmaxf(v10, 0.f); v11 = fmaxf(v11, 0.f);
            }
            size_t o0 = (size_t)row * Ng + col;
            size_t o1 = (size_t)(row + 8) * Ng + col;
            if (outf) {
                *(float2*)(outf + o0) = make_float2(v00, v01);
                *(float2*)(outf + o1) = make_float2(v10, v11);
            } else {
                __nv_bfloat16 h0, m_0, h1, m_1;
                split2(v00, h0, m_0); split2(v01, h1, m_1);
                *(uint32_t*)(outp + o0)       = pk2(h0, h1);
                *(uint32_t*)(outp + ops + o0) = pk2(m_0, m_1);
                split2(v10, h0, m_0); split2(v11, h1, m_1);
                *(uint32_t*)(outp + o1)       = pk2(h0, h1);
                *(uint32_t*)(outp + ops + o1) = pk2(m_0, m_1);
            }
        }
    }
}

// ===================== fp32 SGEMM for batched rescue (R1 body + early exit) ==
template<bool RELU>
__global__ __launch_bounds__(256)
void sgemm_rescue_kernel(const float* __restrict__ A, const float* __restrict__ B,
                         const float* __restrict__ bias, float* __restrict__ C,
                         int Nc, int Kd)
{
    if (blockIdx.y * 128 >= g_flagcnt) return;   // count-proportional cost

    const int BM = 128, BN = 128, BK = 16;
    __shared__ float As[BK][BM];
    __shared__ float Bs[BK][BN];

    const int tid = threadIdx.x;
    const int tm = tid >> 4;
    const int tn = tid & 15;
    const int bm = blockIdx.y;
    const int bn = blockIdx.x;

    const float* Ablk = A + (size_t)bm * BM * Kd;
    const float* Bblk = B + (size_t)bn * BN;

    const int a_row = tid >> 2;
    const int a_col = (tid & 3) * 4;
    const int b_row = tid >> 5;
    const int b_col = (tid & 31) * 4;

    float acc[8][8];
#pragma unroll
    for (int i = 0; i < 8; i++)
#pragma unroll
        for (int j = 0; j < 8; j++) acc[i][j] = 0.f;

    float4 pa0, pa1, pb0, pb1;
    pa0 = *(const float4*)(Ablk + (size_t)a_row        * Kd + a_col);
    pa1 = *(const float4*)(Ablk + (size_t)(a_row + 64) * Kd + a_col);
    pb0 = *(const float4*)(Bblk + (size_t)b_row        * Nc + b_col);
    pb1 = *(const float4*)(Bblk + (size_t)(b_row + 8)  * Nc + b_col);

    for (int k0 = 0; k0 < Kd; k0 += BK) {
        As[a_col + 0][a_row]      = pa0.x;
        As[a_col + 1][a_row]      = pa0.y;
        As[a_col + 2][a_row]      = pa0.z;
        As[a_col + 3][a_row]      = pa0.w;
        As[a_col + 0][a_row + 64] = pa1.x;
        As[a_col + 1][a_row + 64] = pa1.y;
        As[a_col + 2][a_row + 64] = pa1.z;
        As[a_col + 3][a_row + 64] = pa1.w;
        *(float4*)&Bs[b_row][b_col]     = pb0;
        *(float4*)&Bs[b_row + 8][b_col] = pb1;
        __syncthreads();

        if (k0 + BK < Kd) {
            const int kn = k0 + BK;
            pa0 = *(const float4*)(Ablk + (size_t)a_row        * Kd + kn + a_col);
            pa1 = *(const float4*)(Ablk + (size_t)(a_row + 64) * Kd + kn + a_col);
            pb0 = *(const float4*)(Bblk + (size_t)(kn + b_row)     * Nc + b_col);
            pb1 = *(const float4*)(Bblk + (size_t)(kn + b_row + 8) * Nc + b_col);
        }

#pragma unroll
        for (int kk = 0; kk < BK; kk++) {
            float a[8], b[8];
            *(float4*)&a[0] = *(const float4*)&As[kk][tm * 8];
            *(float4*)&a[4] = *(const float4*)&As[kk][tm * 8 + 4];
            *(float4*)&b[0] = *(const float4*)&Bs[kk][tn * 8];
            *(float4*)&b[4] = *(const float4*)&Bs[kk][tn * 8 + 4];
#pragma unroll
            for (int i = 0; i < 8; i++)
#pragma unroll
                for (int j = 0; j < 8; j++) acc[i][j] += a[i] * b[j];
        }
        __syncthreads();
    }

    const int row0 = bm * BM + tm * 8;
    const int col0 = bn * BN + tn * 8;
    float bv[8];
    *(float4*)&bv[0] = *(const float4*)&bias[col0];
    *(float4*)&bv[4] = *(const float4*)&bias[col0 + 4];
#pragma unroll
    for (int i = 0; i < 8; i++) {
        float v[8];
#pragma unroll
        for (int j = 0; j < 8; j++) {
            float t = acc[i][j] + bv[j];
            if (RELU) t = t > 0.f ? t : 0.f;
            v[j] = t;
        }
        float* crow = C + (size_t)(row0 + i) * Nc + col0;
        *(float4*)&crow[0] = *(float4*)&v[0];
        *(float4*)&crow[4] = *(float4*)&v[4];
    }
}

// ===================== fp32 distance path w/ top-2 (verified) ================
__global__ void rownorm256_kernel(const float* __restrict__ X, float* __restrict__ out, int rows)
{
    int gw   = (blockIdx.x * blockDim.x + threadIdx.x) >> 5;
    int lane = threadIdx.x & 31;
    if (gw >= rows) return;
    const float* row = X + (size_t)gw * 256;
    float s = 0.f;
    for (int c = lane * 4; c < 256; c += 128) {
        float4 v = *(const float4*)&row[c];
        s += v.x * v.x + v.y * v.y + v.z * v.z + v.w * v.w;
    }
#pragma unroll
    for (int o = 16; o; o >>= 1) s += __shfl_xor_sync(0xffffffffu, s, o);
    if (!lane) out[gw] = s;
}

__global__ __launch_bounds__(256)
void distmin_kernel(const float* __restrict__ Z, const float* __restrict__ CB,
                    const float* __restrict__ cnorm,
                    float* __restrict__ pval, float* __restrict__ pval2,
                    int* __restrict__ pidx)
{
    const int BM = 128, BN = 128, BK = 16, KD = 256, JG = 1024;
    __shared__ float As[BK][BM];
    __shared__ float Bs[BK][BN];
    __shared__ float s_rv [BM][17];
    __shared__ float s_rv2[BM][17];
    __shared__ int   s_ri [BM][17];
    __shared__ float s_bestv[BM];
    __shared__ float s_bestv2[BM];
    __shared__ int   s_besti[BM];

    const int tid = threadIdx.x;
    const int tm = tid >> 4, tn = tid & 15;
    const int bm  = blockIdx.y;
    const int grp = blockIdx.x;

    if (tid < BM) { s_bestv[tid] = 3.4e38f; s_bestv2[tid] = 3.4e38f; s_besti[tid] = 0; }

    const float* Ablk = Z + (size_t)bm * BM * KD;
    const int t_row = tid >> 2;
    const int t_col = (tid & 3) * 4;

    for (int j0 = grp * JG; j0 < grp * JG + JG; j0 += BN) {
        const float* Bblk = CB + (size_t)j0 * KD;
        float acc[8][8];
#pragma unroll
        for (int i = 0; i < 8; i++)
#pragma unroll
            for (int j = 0; j < 8; j++) acc[i][j] = 0.f;

        float4 pa0, pa1, pb0, pb1;
        pa0 = *(const float4*)(Ablk + (size_t)t_row        * KD + t_col);
        pa1 = *(const float4*)(Ablk + (size_t)(t_row + 64) * KD + t_col);
        pb0 = *(const float4*)(Bblk + (size_t)t_row        * KD + t_col);
        pb1 = *(const float4*)(Bblk + (size_t)(t_row + 64) * KD + t_col);

        for (int k0 = 0; k0 < KD; k0 += BK) {
            __syncthreads();
            As[t_col + 0][t_row]      = pa0.x;
            As[t_col + 1][t_row]      = pa0.y;
            As[t_col + 2][t_row]      = pa0.z;
            As[t_col + 3][t_row]      = pa0.w;
            As[t_col + 0][t_row + 64] = pa1.x;
            As[t_col + 1][t_row + 64] = pa1.y;
            As[t_col + 2][t_row + 64] = pa1.z;
            As[t_col + 3][t_row + 64] = pa1.w;
            Bs[t_col + 0][t_row]      = pb0.x;
            Bs[t_col + 1][t_row]      = pb0.y;
            Bs[t_col + 2][t_row]      = pb0.z;
            Bs[t_col + 3][t_row]      = pb0.w;
            Bs[t_col + 0][t_row + 64] = pb1.x;
            Bs[t_col + 1][t_row + 64] = pb1.y;
            Bs[t_col + 2][t_row + 64] = pb1.z;
            Bs[t_col + 3][t_row + 64] = pb1.w;
            __syncthreads();

            if (k0 + BK < KD) {
                const int kn = k0 + BK;
                pa0 = *(const float4*)(Ablk + (size_t)t_row        * KD + kn + t_col);
                pa1 = *(const float4*)(Ablk + (size_t)(t_row + 64) * KD + kn + t_col);
                pb0 = *(const float4*)(Bblk + (size_t)t_row        * KD + kn + t_col);
                pb1 = *(const float4*)(Bblk + (size_t)(t_row + 64) * KD + kn + t_col);
            }

#pragma unroll
            for (int kk = 0; kk < BK; kk++) {
                float a[8], b[8];
                *(float4*)&a[0] = *(const float4*)&As[kk][tm * 8];
                *(float4*)&a[4] = *(const float4*)&As[kk][tm * 8 + 4];
                *(float4*)&b[0] = *(const float4*)&Bs[kk][tn * 8];
                *(float4*)&b[4] = *(const float4*)&Bs[kk][tn * 8 + 4];
#pragma unroll
                for (int i = 0; i < 8; i++)
#pragma unroll
                    for (int j = 0; j < 8; j++) acc[i][j] += a[i] * b[j];
            }
        }
        __syncthreads();

        float cn[8];
        *(float4*)&cn[0] = *(const float4*)&cnorm[j0 + tn * 8];
        *(float4*)&cn[4] = *(const float4*)&cnorm[j0 + tn * 8 + 4];
#pragma unroll
        for (int i = 0; i < 8; i++) {
            float v1 = 3.4e38f, v2 = 3.4e38f; int i1 = 0;
#pragma unroll
            for (int j = 0; j < 8; j++) {
                float s = cn[j] - 2.f * acc[i][j];
                if (s < v1) { v2 = v1; v1 = s; i1 = j0 + tn * 8 + j; }
                else if (s < v2) v2 = s;
            }
            s_rv [tm * 8 + i][tn] = v1;
            s_rv2[tm * 8 + i][tn] = v2;
            s_ri [tm * 8 + i][tn] = i1;
        }
        __syncthreads();
        if (tid < BM) {
            float V1 = s_bestv[tid], V2 = s_bestv2[tid]; int I1 = s_besti[tid];
#pragma unroll
            for (int t = 0; t < 16; t++) {
                float v1c = s_rv[tid][t], v2c = s_rv2[tid][t];
                if (v1c < V1) { V2 = fminf(V1, v2c); V1 = v1c; I1 = s_ri[tid][t]; }
                else          { V2 = fminf(V2, v1c); }
            }
            s_bestv[tid] = V1; s_bestv2[tid] = V2; s_besti[tid] = I1;
        }
    }
    __syncthreads();
    if (tid < BM) {
        pval [(size_t)grp * NR + bm * BM + tid] = s_bestv[tid];
        pval2[(size_t)grp * NR + bm * BM + tid] = s_bestv2[tid];
        pidx [(size_t)grp * NR + bm * BM + tid] = s_besti[tid];
    }
}

__global__ void zero_flags_kernel() {
    if (threadIdx.x == 0 && blockIdx.x == 0) g_flagcnt = 0;
}

__global__ void combine_kernel(const float* __restrict__ pval, const float* __restrict__ pval2,
                               const int* __restrict__ pidx,
                               const float* __restrict__ znorm,
                               float* __restrict__ minval, int* __restrict__ minidx)
{
    int r = blockIdx.x * blockDim.x + threadIdx.x;
    if (r >= NR) return;
    float V1 = 3.4e38f, V2 = 3.4e38f; int I1 = 0;
#pragma unroll
    for (int g = 0; g < 4; g++) {
        float v1c = pval [(size_t)g * NR + r];
        float v2c = pval2[(size_t)g * NR + r];
        int   i1c = pidx [(size_t)g * NR + r];
        if (v1c < V1) { V2 = fminf(V1, v2c); V1 = v1c; I1 = i1c; }
        else          { V2 = fminf(V2, v1c); }
    }
    float zn = znorm[r];
    minval[r] = zn + V1;
    minidx[r] = I1;
    float d1 = zn + V1, d2 = zn + V2;
    // bf16x2 d-noise ~0.015 abs; margin ~20x noise
    if (d2 - d1 < 0.3f + 1e-3f * (fabsf(d1) + fabsf(d2))) {
        int s = atomicAdd(&g_flagcnt, 1);
        if (s < RESCUE_CAP) g_flaglist[s] = r;
    }
}

// ===================== batched rescue: gather + exact dist ===================
__global__ void gatherx_kernel(const float* __restrict__ x, float* __restrict__ gx)
{
    int q = blockIdx.x;
    int cnt = g_flagcnt; if (cnt > RESCUE_CAP) cnt = RESCUE_CAP;
    if (q >= cnt) return;
    int r = g_flaglist[q];
    int c = threadIdx.x;           // 256 threads x float4 = 1024 floats
    float4 v = *(const float4*)&x[(size_t)r * DIN + c * 4];
    *(float4*)&gx[(size_t)q * DIN + c * 4] = v;
}

// exact fp32 distance+argmin for rescued slot q (one block per slot)
__global__ __launch_bounds__(256)
void rescue_dist_kernel(const float* __restrict__ gz, const float* __restrict__ CB,
                        const float* __restrict__ cnorm,
                        float* __restrict__ minval, int* __restrict__ minidx)
{
    int q = blockIdx.x;
    int cnt = g_flagcnt; if (cnt > RESCUE_CAP) cnt = RESCUE_CAP;
    if (q >= cnt) return;

    __shared__ float sz[DZ];
    __shared__ float rv[256];
    __shared__ int   ri[256];
    const int tid = threadIdx.x;

    sz[tid] = gz[(size_t)q * DZ + tid];
    __syncthreads();

    // znorm via block reduce
    rv[tid] = sz[tid] * sz[tid];
    __syncthreads();
    for (int w = 128; w > 0; w >>= 1) {
        if (tid < w) rv[tid] += rv[tid + w];
        __syncthreads();
    }
    float znorm_q = rv[0];
    __syncthreads();

    float V = 3.4e38f; int I = 0;
    for (int jj = 0; jj < 16; jj++) {
        int j = tid * 16 + jj;                // ascending j per thread
        const float* crow = CB + (size_t)j * DZ;
        float dot = 0.f;
        for (int k = 0; k < DZ; k += 4) {
            float4 c4 = *(const float4*)(crow + k);
            dot += sz[k] * c4.x + sz[k+1] * c4.y + sz[k+2] * c4.z + sz[k+3] * c4.w;
        }
        float s = cnorm[j] - 2.f * dot;
        if (s < V) { V = s; I = j; }
    }
    rv[tid] = V; ri[tid] = I;
    __syncthreads();
    for (int w = 128; w > 0; w >>= 1) {
        if (tid < w) {
            if (rv[tid + w] < rv[tid] ||
                (rv[tid + w] == rv[tid] && ri[tid + w] < ri[tid])) {
                rv[tid] = rv[tid + w]; ri[tid] = ri[tid + w];
            }
        }
        __syncthreads();
    }
    if (tid == 0) {
        int r = g_flaglist[q];
        minval[r] = znorm_q + rv[0];
        minidx[r] = ri[0];
    }
}

// ===================== output kernels ========================================
__global__ void gather_kernel(const float* __restrict__ CB, const int* __restrict__ minidx,
                              float* __restrict__ out)
{
    int r = blockIdx.x;
    int c = threadIdx.x;
    float4 v = *(const float4*)&CB[(size_t)minidx[r] * DZ + c * 4];
    *(float4*)&out[(size_t)r * DZ + c * 4] = v;
}

__global__ void loss_kernel(const float* __restrict__ minval, float* __restrict__ out,
                            int out_size)
{
    __shared__ float sm[512];
    int t = threadIdx.x;
    float s = 0.f;
    for (int i = t; i < NR; i += 512) s += minval[i];
    sm[t] = s;
    __syncthreads();
    for (int w = 256; w > 0; w >>= 1) {
        if (t < w) sm[t] += sm[t + w];
        __syncthreads();
    }
    if (t == 0 && out_size > NR * DZ) out[NR * DZ] = 2.f * sm[0];
}

// ===================== launch ================================================
extern "C" void kernel_launch(void* const* d_in, const int* in_sizes, int n_in,
                              void* d_out, int out_size)
{
    const float* x  = (const float*)d_in[0];
    const float* W1 = (const float*)d_in[1];
    const float* b1 = (const float*)d_in[2];
    const float* W2 = (const float*)d_in[3];
    const float* b2 = (const float*)d_in[4];
    const float* W3 = (const float*)d_in[5];
    const float* b3 = (const float*)d_in[6];
    const float* CB = (const float*)d_in[7];
    float* out = (float*)d_out;

    __nv_bfloat16 *xs, *w1s, *w2s, *w3s, *h1s, *h2s;
    float *z, *znorm, *cnorm, *pval, *pval2, *minval;
    float *gx, *gh1, *gh2, *gz;
    int *pidx, *minidx;
    cudaGetSymbolAddress((void**)&xs,  g_xs);
    cudaGetSymbolAddress((void**)&w1s, g_w1s);
    cudaGetSymbolAddress((void**)&w2s, g_w2s);
    cudaGetSymbolAddress((void**)&w3s, g_w3s);
    cudaGetSymbolAddress((void**)&h1s, g_h1s);
    cudaGetSymbolAddress((void**)&h2s, g_h2s);
    cudaGetSymbolAddress((void**)&z,      g_z);
    cudaGetSymbolAddress((void**)&znorm,  g_znorm);
    cudaGetSymbolAddress((void**)&cnorm,  g_cnorm);
    cudaGetSymbolAddress((void**)&pval,   g_pval);
    cudaGetSymbolAddress((void**)&pval2,  g_pval2);
    cudaGetSymbolAddress((void**)&pidx,   g_pidx);
    cudaGetSymbolAddress((void**)&minval, g_minval);
    cudaGetSymbolAddress((void**)&minidx, g_minidx);
    cudaGetSymbolAddress((void**)&gx,  g_gx);
    cudaGetSymbolAddress((void**)&gh1, g_gh1);
    cudaGetSymbolAddress((void**)&gh2, g_gh2);
    cudaGetSymbolAddress((void**)&gz,  g_gz);

    cudaFuncSetAttribute(gemm_b2_mma_kernel, cudaFuncAttributeMaxDynamicSharedMemorySize,
                         GEMM_SMEM_BYTES);

    const size_t ps_x  = (size_t)NR * DIN;
    const size_t ps_w1 = (size_t)DH * DIN;
    const size_t ps_w2 = (size_t)DH * DH;
    const size_t ps_w3 = (size_t)DZ * DH;
    const size_t ps_h  = (size_t)NR * DH;

    // 2-limb splits
    split_kernel<<<(unsigned)(ps_x / 4 / 256), 256>>>(x, xs, ps_x, ps_x);
    splitT_kernel<<<dim3(DH / 32, DIN / 32), dim3(32, 8)>>>(W1, w1s, DIN, DH, ps_w1);
    splitT_kernel<<<dim3(DH / 32, DH  / 32), dim3(32, 8)>>>(W2, w2s, DH,  DH, ps_w2);
    splitT_kernel<<<dim3(DZ / 32, DH  / 32), dim3(32, 8)>>>(W3, w3s, DH,  DZ, ps_w3);

    // MLP on HMMA (bf16x2, 3 products)
    gemm_b2_mma_kernel<<<dim3(DH / 128, NR / 128), 256, GEMM_SMEM_BYTES>>>(
        xs, ps_x, w1s, ps_w1, b1, h1s, ps_h, nullptr, DIN, DH, 1);
    gemm_b2_mma_kernel<<<dim3(DH / 128, NR / 128), 256, GEMM_SMEM_BYTES>>>(
        h1s, ps_h, w2s, ps_w2, b2, h2s, ps_h, nullptr, DH, DH, 0);
    gemm_b2_mma_kernel<<<dim3(DZ / 128, NR / 128), 256, GEMM_SMEM_BYTES>>>(
        h2s, ps_h, w3s, ps_w3, b3, nullptr, 0, z, DH, DZ, 0);

    // norms + fused distance/argmin (top-2)
    rownorm256_kernel<<<(KCB * 32) / 256, 256>>>(CB, cnorm, KCB);
    rownorm256_kernel<<<(NR  * 32) / 256, 256>>>(z,  znorm, NR);
    zero_flags_kernel<<<1, 32>>>();
    distmin_kernel<<<dim3(4, NR / 128), 256>>>(z, CB, cnorm, pval, pval2, pidx);
    combine_kernel<<<NR / 256, 256>>>(pval, pval2, pidx, znorm, minval, minidx);

    // batched exact-fp32 rescue: gather rows, re-run R1 SGEMM chain, re-argmin
    gatherx_kernel<<<RESCUE_CAP, 256>>>(x, gx);
    sgemm_rescue_kernel<true ><<<dim3(DH / 128, RESCUE_CAP / 128), 256>>>(gx,  W1, b1, gh1, DH, DIN);
    sgemm_rescue_kernel<false><<<dim3(DH / 128, RESCUE_CAP / 128), 256>>>(gh1, W2, b2, gh2, DH, DH);
    sgemm_rescue_kernel<false><<<dim3(DZ / 128, RESCUE_CAP / 128), 256>>>(gh2, W3, b3, gz,  DZ, DH);
    rescue_dist_kernel<<<RESCUE_CAP, 256>>>(gz, CB, cnorm, minval, minidx);

    // outputs
    gather_kernel<<<NR, 64>>>(CB, minidx, out);
    loss_kernel<<<1, 512>>>(minval, out, out_size);
}

// round 14
// speedup vs baseline: 3.6970x; 1.2121x over previous
#include <cuda_runtime.h>
#include <cuda_bf16.h>
#include <cstdint>

// Problem constants
#define NR   16384
#define DIN  1024
#define DH   4096
#define DZ   256
#define KCB  4096
#define RESCUE_CAP 8192

// ===================== scratch (device globals) ==============================
__device__ float g_xr [(size_t)NR * DIN];    // tf32-rounded x
__device__ float g_w1t[(size_t)DH * DIN];    // tf32-rounded W1^T
__device__ float g_w2t[(size_t)DH * DH];     // tf32-rounded W2^T
__device__ float g_w3t[(size_t)DZ * DH];     // tf32-rounded W3^T
__device__ float g_h1r[(size_t)NR * DH];     // tf32-rounded h1
__device__ float g_h2r[(size_t)NR * DH];     // tf32-rounded h2
__device__ float g_z [NR * DZ];
__device__ float g_znorm[NR];
__device__ float g_cnorm[KCB];
__device__ float g_pval [4 * NR];
__device__ float g_pval2[4 * NR];
__device__ int   g_pidx[4 * NR];
__device__ float g_minval[NR];
__device__ int   g_minidx[NR];
__device__ int   g_flagcnt;
__device__ int   g_flaglist[RESCUE_CAP];
// batched rescue buffers
__device__ float g_gx [(size_t)RESCUE_CAP * DIN];
__device__ float g_gh1[(size_t)RESCUE_CAP * DH];
__device__ float g_gh2[(size_t)RESCUE_CAP * DH];
__device__ float g_gz [(size_t)RESCUE_CAP * DZ];

// ===================== helpers ===============================================
__device__ __forceinline__ uint32_t smem_to_u32(const void* smem_ptr) {
    uint32_t addr;
    asm("{ .reg .u64 tmp; cvta.to.shared.u64 tmp, %1; cvt.u32.u64 %0, tmp; }"
        : "=r"(addr) : "l"(smem_ptr));
    return addr;
}
__device__ __forceinline__ float tf32r(float v) {
    uint32_t u;
    asm("cvt.rna.tf32.f32 %0, %1;" : "=r"(u) : "f"(v));
    return __uint_as_float(u);
}

#define MMATF32(d, a, b0, b1) \
    asm volatile("mma.sync.aligned.m16n8k8.row.col.f32.tf32.tf32.f32 " \
        "{%0,%1,%2,%3}, {%4,%5,%6,%7}, {%8,%9}, {%0,%1,%2,%3};" \
        : "+f"((d)[0]), "+f"((d)[1]), "+f"((d)[2]), "+f"((d)[3]) \
        : "r"((a)[0]), "r"((a)[1]), "r"((a)[2]), "r"((a)[3]), "r"(b0), "r"(b1))

// ===================== prep kernels (tf32 rounding) ==========================
__global__ void roundcvt_kernel(const float* __restrict__ in, float* __restrict__ out,
                                size_t n)
{
    size_t i = ((size_t)blockIdx.x * blockDim.x + threadIdx.x) * 4;
    if (i >= n) return;
    float4 v = *(const float4*)(in + i);
    v.x = tf32r(v.x); v.y = tf32r(v.y); v.z = tf32r(v.z); v.w = tf32r(v.w);
    *(float4*)(out + i) = v;
}

// transpose + round: W[K][N] fp32 -> out[N][K] tf32-rounded
__global__ void roundT_kernel(const float* __restrict__ W, float* __restrict__ out,
                              int K, int N)
{
    __shared__ float tile[32][33];
    int k0 = blockIdx.y * 32, n0 = blockIdx.x * 32;
    int tx = threadIdx.x, ty = threadIdx.y;   // 32 x 8
#pragma unroll
    for (int dy = 0; dy < 32; dy += 8)
        tile[ty + dy][tx] = W[(size_t)(k0 + ty + dy) * N + n0 + tx];
    __syncthreads();
#pragma unroll
    for (int dy = 0; dy < 32; dy += 8) {
        int n = n0 + ty + dy, k = k0 + tx;
        out[(size_t)n * K + k] = tf32r(tile[tx][ty + dy]);
    }
}

// ===================== tf32 single-product mma.sync GEMM =====================
// D[M,N] fp32 = A_tf32[M,K] @ B_tf32[N,K]^T.  CTA 128x128, BK=32, 2-stage
// cp.async, 8 warps (warp tile 64x32), 2 CTA/SM.
// SMEM tiles: A[128][36f], B[128][36f]  (pitch 36 floats = 144B, 16B-aligned,
// bank = (4r + c + 4j) mod 32 distinct across warp -> conflict-free scalar LDS)
#define TPITCH 36
#define TTILE  (128 * TPITCH * 4)      // 18432 B
#define TSTG   (2 * TTILE)             // 36864 B per stage
#define GEMM_SMEM_BYTES (2 * TSTG)     // 73728

__global__ __launch_bounds__(256, 2)
void gemm_tf32_kernel(const float* __restrict__ Ar,   // [M][Kg] tf32-rounded
                      const float* __restrict__ Br,   // [N][Kg] tf32-rounded (W^T)
                      const float* __restrict__ bias,
                      float* __restrict__ outr,       // tf32-rounded out (h layers)
                      float* __restrict__ outf,       // exact fp32 out (z layer)
                      int Kg, int Ng, int relu)
{
    extern __shared__ char smem[];
    const uint32_t sb = smem_to_u32(smem);
    const int tid = threadIdx.x;
    const int wid = tid >> 5, lane = tid & 31;
    const int wm = wid >> 2;          // 0..1  (warp row: 64 rows)
    const int wn = wid & 3;           // 0..3  (warp col: 32 cols)
    const int m0 = blockIdx.y * 128, n0 = blockIdx.x * 128;

    const int fr = lane >> 2;         // fragment row/col-group 0..7
    const int fc = lane & 3;          // fragment k-sub 0..3

    const float* Abase = Ar + (size_t)m0 * Kg;
    const float* Bbase = Br + (size_t)n0 * Kg;
    const int nIt = Kg >> 5;

    // stage loader: 2 tiles x 128 rows x 8 chunks(16B) = 2048 chunks
    auto load_stage = [&](int it) {
        const uint32_t dstb = sb + (uint32_t)(it & 1) * TSTG;
        const int k0 = it << 5;
#pragma unroll
        for (int t = 0; t < 8; t++) {
            int id = tid + t * 256;          // 0..2047
            int half = id >> 10;             // 0=A, 1=B
            int rem = id & 1023;
            int r = rem >> 3;                // row 0..127
            int c = rem & 7;                 // chunk 0..7 (4 floats each)
            const float* src = (half ? Bbase : Abase) + (size_t)r * Kg + k0 + c * 4;
            uint32_t dst = dstb + (uint32_t)half * TTILE + (uint32_t)(r * 144 + c * 16);
            asm volatile("cp.async.cg.shared.global [%0], [%1], 16;"
                         :: "r"(dst), "l"(src) : "memory");
        }
        asm volatile("cp.async.commit_group;" ::: "memory");
    };

    float acc[4][4][4];
#pragma unroll
    for (int i = 0; i < 4; i++)
#pragma unroll
        for (int j = 0; j < 4; j++)
#pragma unroll
            for (int q = 0; q < 4; q++) acc[i][j][q] = 0.f;

    load_stage(0);
    if (nIt > 1) load_stage(1);

    for (int it = 0; it < nIt; it++) {
        if (it + 1 < nIt) asm volatile("cp.async.wait_group 1;" ::: "memory");
        else              asm volatile("cp.async.wait_group 0;" ::: "memory");
        __syncthreads();

        const float* sA = (const float*)(smem + (size_t)(it & 1) * TSTG);
        const float* sB = (const float*)(smem + (size_t)(it & 1) * TSTG + TTILE);

#pragma unroll
        for (int kk = 0; kk < 4; kk++) {           // k8 blocks within BK=32
            const int kb = kk * 8;
            // B fragments: col n = wn*32 + ni*8 + fr ; k = kb + fc (+4)
            uint32_t Bf[4][2];
#pragma unroll
            for (int ni = 0; ni < 4; ni++) {
                const float* bp = sB + (size_t)(wn * 32 + ni * 8 + fr) * TPITCH + kb + fc;
                Bf[ni][0] = __float_as_uint(bp[0]);
                Bf[ni][1] = __float_as_uint(bp[4]);
            }
#pragma unroll
            for (int mi = 0; mi < 4; mi++) {
                // A fragments: row = wm*64 + mi*16 + fr (+8) ; k = kb + fc (+4)
                const float* ap0 = sA + (size_t)(wm * 64 + mi * 16 + fr) * TPITCH + kb + fc;
                const float* ap1 = ap0 + 8 * TPITCH;
                uint32_t Af[4];
                Af[0] = __float_as_uint(ap0[0]);
                Af[1] = __float_as_uint(ap1[0]);
                Af[2] = __float_as_uint(ap0[4]);
                Af[3] = __float_as_uint(ap1[4]);
#pragma unroll
                for (int ni = 0; ni < 4; ni++)
                    MMATF32(acc[mi][ni], Af, Bf[ni][0], Bf[ni][1]);
            }
        }
        __syncthreads();
        if (it + 2 < nIt) load_stage(it + 2);
    }

    // ---- epilogue ----
    const int rbase = m0 + wm * 64 + fr;
    const int cbase = n0 + wn * 32 + fc * 2;
#pragma unroll
    for (int mi = 0; mi < 4; mi++) {
#pragma unroll
        for (int ni = 0; ni < 4; ni++) {
            int row = rbase + mi * 16;
            int col = cbase + ni * 8;
            float b0 = bias[col], b1 = bias[col + 1];
            float v00 = acc[mi][ni][0] + b0, v01 = acc[mi][ni][1] + b1;
            float v10 = acc[mi][ni][2] + b0, v11 = acc[mi][ni][3] + b1;
            if (relu) {
                v00 = fmaxf(v00, 0.f); v01 = fmaxf(v01, 0.f);
                v10 = fmaxf(v10, 0.f); v11 = fmaxf(v11, 0.f);
            }
            size_t o0 = (size_t)row * Ng + col;
            size_t o1 = (size_t)(row + 8) * Ng + col;
            if (outf) {
                *(float2*)(outf + o0) = make_float2(v00, v01);
                *(float2*)(outf + o1) = make_float2(v10, v11);
            } else {
                *(float2*)(outr + o0) = make_float2(tf32r(v00), tf32r(v01));
                *(float2*)(outr + o1) = make_float2(tf32r(v10), tf32r(v11));
            }
        }
    }
}

// ===================== fp32 SGEMM for batched rescue (R12-verified) ==========
template<bool RELU>
__global__ __launch_bounds__(256)
void sgemm_rescue_kernel(const float* __restrict__ A, const float* __restrict__ B,
                         const float* __restrict__ bias, float* __restrict__ C,
                         int Nc, int Kd)
{
    if (blockIdx.y * 128 >= g_flagcnt) return;   // count-proportional cost

    const int BM = 128, BN = 128, BK = 16;
    __shared__ float As[BK][BM];
    __shared__ float Bs[BK][BN];

    const int tid = threadIdx.x;
    const int tm = tid >> 4;
    const int tn = tid & 15;
    const int bm = blockIdx.y;
    const int bn = blockIdx.x;

    const float* Ablk = A + (size_t)bm * BM * Kd;
    const float* Bblk = B + (size_t)bn * BN;

    const int a_row = tid >> 2;
    const int a_col = (tid & 3) * 4;
    const int b_row = tid >> 5;
    const int b_col = (tid & 31) * 4;

    float acc[8][8];
#pragma unroll
    for (int i = 0; i < 8; i++)
#pragma unroll
        for (int j = 0; j < 8; j++) acc[i][j] = 0.f;

    float4 pa0, pa1, pb0, pb1;
    pa0 = *(const float4*)(Ablk + (size_t)a_row        * Kd + a_col);
    pa1 = *(const float4*)(Ablk + (size_t)(a_row + 64) * Kd + a_col);
    pb0 = *(const float4*)(Bblk + (size_t)b_row        * Nc + b_col);
    pb1 = *(const float4*)(Bblk + (size_t)(b_row + 8)  * Nc + b_col);

    for (int k0 = 0; k0 < Kd; k0 += BK) {
        As[a_col + 0][a_row]      = pa0.x;
        As[a_col + 1][a_row]      = pa0.y;
        As[a_col + 2][a_row]      = pa0.z;
        As[a_col + 3][a_row]      = pa0.w;
        As[a_col + 0][a_row + 64] = pa1.x;
        As[a_col + 1][a_row + 64] = pa1.y;
        As[a_col + 2][a_row + 64] = pa1.z;
        As[a_col + 3][a_row + 64] = pa1.w;
        *(float4*)&Bs[b_row][b_col]     = pb0;
        *(float4*)&Bs[b_row + 8][b_col] = pb1;
        __syncthreads();

        if (k0 + BK < Kd) {
            const int kn = k0 + BK;
            pa0 = *(const float4*)(Ablk + (size_t)a_row        * Kd + kn + a_col);
            pa1 = *(const float4*)(Ablk + (size_t)(a_row + 64) * Kd + kn + a_col);
            pb0 = *(const float4*)(Bblk + (size_t)(kn + b_row)     * Nc + b_col);
            pb1 = *(const float4*)(Bblk + (size_t)(kn + b_row + 8) * Nc + b_col);
        }

#pragma unroll
        for (int kk = 0; kk < BK; kk++) {
            float a[8], b[8];
            *(float4*)&a[0] = *(const float4*)&As[kk][tm * 8];
            *(float4*)&a[4] = *(const float4*)&As[kk][tm * 8 + 4];
            *(float4*)&b[0] = *(const float4*)&Bs[kk][tn * 8];
            *(float4*)&b[4] = *(const float4*)&Bs[kk][tn * 8 + 4];
#pragma unroll
            for (int i = 0; i < 8; i++)
#pragma unroll
                for (int j = 0; j < 8; j++) acc[i][j] += a[i] * b[j];
        }
        __syncthreads();
    }

    const int row0 = bm * BM + tm * 8;
    const int col0 = bn * BN + tn * 8;
    float bv[8];
    *(float4*)&bv[0] = *(const float4*)&bias[col0];
    *(float4*)&bv[4] = *(const float4*)&bias[col0 + 4];
#pragma unroll
    for (int i = 0; i < 8; i++) {
        float v[8];
#pragma unroll
        for (int j = 0; j < 8; j++) {
            float t = acc[i][j] + bv[j];
            if (RELU) t = t > 0.f ? t : 0.f;
            v[j] = t;
        }
        float* crow = C + (size_t)(row0 + i) * Nc + col0;
        *(float4*)&crow[0] = *(float4*)&v[0];
        *(float4*)&crow[4] = *(float4*)&v[4];
    }
}

// ===================== fp32 distance path w/ top-2 (verified) ================
__global__ void rownorm256_kernel(const float* __restrict__ X, float* __restrict__ out, int rows)
{
    int gw   = (blockIdx.x * blockDim.x + threadIdx.x) >> 5;
    int lane = threadIdx.x & 31;
    if (gw >= rows) return;
    const float* row = X + (size_t)gw * 256;
    float s = 0.f;
    for (int c = lane * 4; c < 256; c += 128) {
        float4 v = *(const float4*)&row[c];
        s += v.x * v.x + v.y * v.y + v.z * v.z + v.w * v.w;
    }
#pragma unroll
    for (int o = 16; o; o >>= 1) s += __shfl_xor_sync(0xffffffffu, s, o);
    if (!lane) out[gw] = s;
}

__global__ __launch_bounds__(256)
void distmin_kernel(const float* __restrict__ Z, const float* __restrict__ CB,
                    const float* __restrict__ cnorm,
                    float* __restrict__ pval, float* __restrict__ pval2,
                    int* __restrict__ pidx)
{
    const int BM = 128, BN = 128, BK = 16, KD = 256, JG = 1024;
    __shared__ float As[BK][BM];
    __shared__ float Bs[BK][BN];
    __shared__ float s_rv [BM][17];
    __shared__ float s_rv2[BM][17];
    __shared__ int   s_ri [BM][17];
    __shared__ float s_bestv[BM];
    __shared__ float s_bestv2[BM];
    __shared__ int   s_besti[BM];

    const int tid = threadIdx.x;
    const int tm = tid >> 4, tn = tid & 15;
    const int bm  = blockIdx.y;
    const int grp = blockIdx.x;

    if (tid < BM) { s_bestv[tid] = 3.4e38f; s_bestv2[tid] = 3.4e38f; s_besti[tid] = 0; }

    const float* Ablk = Z + (size_t)bm * BM * KD;
    const int t_row = tid >> 2;
    const int t_col = (tid & 3) * 4;

    for (int j0 = grp * JG; j0 < grp * JG + JG; j0 += BN) {
        const float* Bblk = CB + (size_t)j0 * KD;
        float acc[8][8];
#pragma unroll
        for (int i = 0; i < 8; i++)
#pragma unroll
            for (int j = 0; j < 8; j++) acc[i][j] = 0.f;

        float4 pa0, pa1, pb0, pb1;
        pa0 = *(const float4*)(Ablk + (size_t)t_row        * KD + t_col);
        pa1 = *(const float4*)(Ablk + (size_t)(t_row + 64) * KD + t_col);
        pb0 = *(const float4*)(Bblk + (size_t)t_row        * KD + t_col);
        pb1 = *(const float4*)(Bblk + (size_t)(t_row + 64) * KD + t_col);

        for (int k0 = 0; k0 < KD; k0 += BK) {
            __syncthreads();
            As[t_col + 0][t_row]      = pa0.x;
            As[t_col + 1][t_row]      = pa0.y;
            As[t_col + 2][t_row]      = pa0.z;
            As[t_col + 3][t_row]      = pa0.w;
            As[t_col + 0][t_row + 64] = pa1.x;
            As[t_col + 1][t_row + 64] = pa1.y;
            As[t_col + 2][t_row + 64] = pa1.z;
            As[t_col + 3][t_row + 64] = pa1.w;
            Bs[t_col + 0][t_row]      = pb0.x;
            Bs[t_col + 1][t_row]      = pb0.y;
            Bs[t_col + 2][t_row]      = pb0.z;
            Bs[t_col + 3][t_row]      = pb0.w;
            Bs[t_col + 0][t_row + 64] = pb1.x;
            Bs[t_col + 1][t_row + 64] = pb1.y;
            Bs[t_col + 2][t_row + 64] = pb1.z;
            Bs[t_col + 3][t_row + 64] = pb1.w;
            __syncthreads();

            if (k0 + BK < KD) {
                const int kn = k0 + BK;
                pa0 = *(const float4*)(Ablk + (size_t)t_row        * KD + kn + t_col);
                pa1 = *(const float4*)(Ablk + (size_t)(t_row + 64) * KD + kn + t_col);
                pb0 = *(const float4*)(Bblk + (size_t)t_row        * KD + kn + t_col);
                pb1 = *(const float4*)(Bblk + (size_t)(t_row + 64) * KD + kn + t_col);
            }

#pragma unroll
            for (int kk = 0; kk < BK; kk++) {
                float a[8], b[8];
                *(float4*)&a[0] = *(const float4*)&As[kk][tm * 8];
                *(float4*)&a[4] = *(const float4*)&As[kk][tm * 8 + 4];
                *(float4*)&b[0] = *(const float4*)&Bs[kk][tn * 8];
                *(float4*)&b[4] = *(const float4*)&Bs[kk][tn * 8 + 4];
#pragma unroll
                for (int i = 0; i < 8; i++)
#pragma unroll
                    for (int j = 0; j < 8; j++) acc[i][j] += a[i] * b[j];
            }
        }
        __syncthreads();

        float cn[8];
        *(float4*)&cn[0] = *(const float4*)&cnorm[j0 + tn * 8];
        *(float4*)&cn[4] = *(const float4*)&cnorm[j0 + tn * 8 + 4];
#pragma unroll
        for (int i = 0; i < 8; i++) {
            float v1 = 3.4e38f, v2 = 3.4e38f; int i1 = 0;
#pragma unroll
            for (int j = 0; j < 8; j++) {
                float s = cn[j] - 2.f * acc[i][j];
                if (s < v1) { v2 = v1; v1 = s; i1 = j0 + tn * 8 + j; }
                else if (s < v2) v2 = s;
            }
            s_rv [tm * 8 + i][tn] = v1;
            s_rv2[tm * 8 + i][tn] = v2;
            s_ri [tm * 8 + i][tn] = i1;
        }
        __syncthreads();
        if (tid < BM) {
            float V1 = s_bestv[tid], V2 = s_bestv2[tid]; int I1 = s_besti[tid];
#pragma unroll
            for (int t = 0; t < 16; t++) {
                float v1c = s_rv[tid][t], v2c = s_rv2[tid][t];
                if (v1c < V1) { V2 = fminf(V1, v2c); V1 = v1c; I1 = s_ri[tid][t]; }
                else          { V2 = fminf(V2, v1c); }
            }
            s_bestv[tid] = V1; s_bestv2[tid] = V2; s_besti[tid] = I1;
        }
    }
    __syncthreads();
    if (tid < BM) {
        pval [(size_t)grp * NR + bm * BM + tid] = s_bestv[tid];
        pval2[(size_t)grp * NR + bm * BM + tid] = s_bestv2[tid];
        pidx [(size_t)grp * NR + bm * BM + tid] = s_besti[tid];
    }
}

__global__ void zero_flags_kernel() {
    if (threadIdx.x == 0 && blockIdx.x == 0) g_flagcnt = 0;
}

__global__ void combine_kernel(const float* __restrict__ pval, const float* __restrict__ pval2,
                               const int* __restrict__ pidx,
                               const float* __restrict__ znorm,
                               float* __restrict__ minval, int* __restrict__ minidx)
{
    int r = blockIdx.x * blockDim.x + threadIdx.x;
    if (r >= NR) return;
    float V1 = 3.4e38f, V2 = 3.4e38f; int I1 = 0;
#pragma unroll
    for (int g = 0; g < 4; g++) {
        float v1c = pval [(size_t)g * NR + r];
        float v2c = pval2[(size_t)g * NR + r];
        int   i1c = pidx [(size_t)g * NR + r];
        if (v1c < V1) { V2 = fminf(V1, v2c); V1 = v1c; I1 = i1c; }
        else          { V2 = fminf(V2, v1c); }
    }
    float zn = znorm[r];
    minval[r] = zn + V1;
    minidx[r] = I1;
    float d1 = zn + V1, d2 = zn + V2;
    // tf32 d-noise sigma ~0.05 abs; margin 0.5 = 10 sigma
    if (d2 - d1 < 0.5f + 1e-3f * (fabsf(d1) + fabsf(d2))) {
        int s = atomicAdd(&g_flagcnt, 1);
        if (s < RESCUE_CAP) g_flaglist[s] = r;
    }
}

// ===================== batched rescue: gather + exact dist ===================
__global__ void gatherx_kernel(const float* __restrict__ x, float* __restrict__ gx)
{
    int q = blockIdx.x;
    int cnt = g_flagcnt; if (cnt > RESCUE_CAP) cnt = RESCUE_CAP;
    if (q >= cnt) return;
    int r = g_flaglist[q];
    int c = threadIdx.x;
    float4 v = *(const float4*)&x[(size_t)r * DIN + c * 4];
    *(float4*)&gx[(size_t)q * DIN + c * 4] = v;
}

__global__ __launch_bounds__(256)
void rescue_dist_kernel(const float* __restrict__ gz, const float* __restrict__ CB,
                        const float* __restrict__ cnorm,
                        float* __restrict__ minval, int* __restrict__ minidx)
{
    int q = blockIdx.x;
    int cnt = g_flagcnt; if (cnt > RESCUE_CAP) cnt = RESCUE_CAP;
    if (q >= cnt) return;

    __shared__ float sz[DZ];
    __shared__ float rv[256];
    __shared__ int   ri[256];
    const int tid = threadIdx.x;

    sz[tid] = gz[(size_t)q * DZ + tid];
    __syncthreads();

    rv[tid] = sz[tid] * sz[tid];
    __syncthreads();
    for (int w = 128; w > 0; w >>= 1) {
        if (tid < w) rv[tid] += rv[tid + w];
        __syncthreads();
    }
    float znorm_q = rv[0];
    __syncthreads();

    float V = 3.4e38f; int I = 0;
    for (int jj = 0; jj < 16; jj++) {
        int j = tid * 16 + jj;
        const float* crow = CB + (size_t)j * DZ;
        float dot = 0.f;
        for (int k = 0; k < DZ; k += 4) {
            float4 c4 = *(const float4*)(crow + k);
            dot += sz[k] * c4.x + sz[k+1] * c4.y + sz[k+2] * c4.z + sz[k+3] * c4.w;
        }
        float s = cnorm[j] - 2.f * dot;
        if (s < V) { V = s; I = j; }
    }
    rv[tid] = V; ri[tid] = I;
    __syncthreads();
    for (int w = 128; w > 0; w >>= 1) {
        if (tid < w) {
            if (rv[tid + w] < rv[tid] ||
                (rv[tid + w] == rv[tid] && ri[tid + w] < ri[tid])) {
                rv[tid] = rv[tid + w]; ri[tid] = ri[tid + w];
            }
        }
        __syncthreads();
    }
    if (tid == 0) {
        int r = g_flaglist[q];
        minval[r] = znorm_q + rv[0];
        minidx[r] = ri[0];
    }
}

// ===================== output kernels ========================================
__global__ void gather_kernel(const float* __restrict__ CB, const int* __restrict__ minidx,
                              float* __restrict__ out)
{
    int r = blockIdx.x;
    int c = threadIdx.x;
    float4 v = *(const float4*)&CB[(size_t)minidx[r] * DZ + c * 4];
    *(float4*)&out[(size_t)r * DZ + c * 4] = v;
}

__global__ void loss_kernel(const float* __restrict__ minval, float* __restrict__ out,
                            int out_size)
{
    __shared__ float sm[512];
    int t = threadIdx.x;
    float s = 0.f;
    for (int i = t; i < NR; i += 512) s += minval[i];
    sm[t] = s;
    __syncthreads();
    for (int w = 256; w > 0; w >>= 1) {
        if (t < w) sm[t] += sm[t + w];
        __syncthreads();
    }
    if (t == 0 && out_size > NR * DZ) out[NR * DZ] = 2.f * sm[0];
}

// ===================== launch ================================================
extern "C" void kernel_launch(void* const* d_in, const int* in_sizes, int n_in,
                              void* d_out, int out_size)
{
    const float* x  = (const float*)d_in[0];
    const float* W1 = (const float*)d_in[1];
    const float* b1 = (const float*)d_in[2];
    const float* W2 = (const float*)d_in[3];
    const float* b2 = (const float*)d_in[4];
    const float* W3 = (const float*)d_in[5];
    const float* b3 = (const float*)d_in[6];
    const float* CB = (const float*)d_in[7];
    float* out = (float*)d_out;

    float *xr, *w1t, *w2t, *w3t, *h1r, *h2r;
    float *z, *znorm, *cnorm, *pval, *pval2, *minval;
    float *gx, *gh1, *gh2, *gz;
    int *pidx, *minidx;
    cudaGetSymbolAddress((void**)&xr,  g_xr);
    cudaGetSymbolAddress((void**)&w1t, g_w1t);
    cudaGetSymbolAddress((void**)&w2t, g_w2t);
    cudaGetSymbolAddress((void**)&w3t, g_w3t);
    cudaGetSymbolAddress((void**)&h1r, g_h1r);
    cudaGetSymbolAddress((void**)&h2r, g_h2r);
    cudaGetSymbolAddress((void**)&z,      g_z);
    cudaGetSymbolAddress((void**)&znorm,  g_znorm);
    cudaGetSymbolAddress((void**)&cnorm,  g_cnorm);
    cudaGetSymbolAddress((void**)&pval,   g_pval);
    cudaGetSymbolAddress((void**)&pval2,  g_pval2);
    cudaGetSymbolAddress((void**)&pidx,   g_pidx);
    cudaGetSymbolAddress((void**)&minval, g_minval);
    cudaGetSymbolAddress((void**)&minidx, g_minidx);
    cudaGetSymbolAddress((void**)&gx,  g_gx);
    cudaGetSymbolAddress((void**)&gh1, g_gh1);
    cudaGetSymbolAddress((void**)&gh2, g_gh2);
    cudaGetSymbolAddress((void**)&gz,  g_gz);

    cudaFuncSetAttribute(gemm_tf32_kernel, cudaFuncAttributeMaxDynamicSharedMemorySize,
                         GEMM_SMEM_BYTES);

    const size_t n_x = (size_t)NR * DIN;

    // tf32 prep
    roundcvt_kernel<<<(unsigned)(n_x / 4 / 256), 256>>>(x, xr, n_x);
    roundT_kernel<<<dim3(DH / 32, DIN / 32), dim3(32, 8)>>>(W1, w1t, DIN, DH);
    roundT_kernel<<<dim3(DH / 32, DH  / 32), dim3(32, 8)>>>(W2, w2t, DH,  DH);
    roundT_kernel<<<dim3(DZ / 32, DH  / 32), dim3(32, 8)>>>(W3, w3t, DH,  DZ);

    // MLP on tf32 mma.sync (single product)
    gemm_tf32_kernel<<<dim3(DH / 128, NR / 128), 256, GEMM_SMEM_BYTES>>>(
        xr,  w1t, b1, h1r, nullptr, DIN, DH, 1);
    gemm_tf32_kernel<<<dim3(DH / 128, NR / 128), 256, GEMM_SMEM_BYTES>>>(
        h1r, w2t, b2, h2r, nullptr, DH, DH, 0);
    gemm_tf32_kernel<<<dim3(DZ / 128, NR / 128), 256, GEMM_SMEM_BYTES>>>(
        h2r, w3t, b3, nullptr, z, DH, DZ, 0);

    // norms + fused distance/argmin (top-2)
    rownorm256_kernel<<<(KCB * 32) / 256, 256>>>(CB, cnorm, KCB);
    rownorm256_kernel<<<(NR  * 32) / 256, 256>>>(z,  znorm, NR);
    zero_flags_kernel<<<1, 32>>>();
    distmin_kernel<<<dim3(4, NR / 128), 256>>>(z, CB, cnorm, pval, pval2, pidx);
    combine_kernel<<<NR / 256, 256>>>(pval, pval2, pidx, znorm, minval, minidx);

    // batched exact-fp32 rescue
    gatherx_kernel<<<RESCUE_CAP, 256>>>(x, gx);
    sgemm_rescue_kernel<true ><<<dim3(DH / 128, RESCUE_CAP / 128), 256>>>(gx,  W1, b1, gh1, DH, DIN);
    sgemm_rescue_kernel<false><<<dim3(DH / 128, RESCUE_CAP / 128), 256>>>(gh1, W2, b2, gh2, DH, DH);
    sgemm_rescue_kernel<false><<<dim3(DZ / 128, RESCUE_CAP / 128), 256>>>(gh2, W3, b3, gz,  DZ, DH);
    rescue_dist_kernel<<<RESCUE_CAP, 256>>>(gz, CB, cnorm, minval, minidx);

    // outputs
    gather_kernel<<<NR, 64>>>(CB, minidx, out);
    loss_kernel<<<1, 512>>>(minval, out, out_size);
}